// round 10
// baseline (speedup 1.0000x reference)
#include <cuda_runtime.h>
#include <cstdint>

// Problem constants (B=1, N=4, C=16, D=64, H=128, W=128)
#define NCTX 4
#define CH   16
#define VOX  (64 * 128 * 128)   // 1,048,576 voxels
#define VPT  2                  // voxels per thread (float2)
#define TPB  256
#define NSM  148
#define CTAS_PER_SM 4
#define GRID (NSM * CTAS_PER_SM)            // 592 persistent CTAs
#define NTILES (VOX / (TPB * VPT))          // 2048 tiles
#define V2   (VOX / 2)                      // float2 elements per slab-plane

// cp.async ring: 4 slots x 5 slabs x TPB float2 = 40KB
#define SLOTS 4
#define SLABS 5
#define LOOKAHEAD 3

__device__ __forceinline__ void cp8(uint32_t dst_smem, const float2* src) {
    asm volatile("cp.async.ca.shared.global [%0], [%1], 8;"
                 :: "r"(dst_smem), "l"(src));
}
__device__ __forceinline__ void cp_commit() {
    asm volatile("cp.async.commit_group;" ::: "memory");
}
__device__ __forceinline__ void cp_wait2() {
    asm volatile("cp.async.wait_group 2;" ::: "memory");
}

__global__ __launch_bounds__(TPB, CTAS_PER_SM) void volattn3d_kernel(
    const float* __restrict__ q,      // [C][V]
    const float* __restrict__ k,      // [N][C][V]
    const float* __restrict__ v,      // [N][C][V]
    const float* __restrict__ w_proj, // [C][C]
    const float* __restrict__ b_proj, // [C]
    float* __restrict__ out)          // [C][V]
{
    __shared__ float sw[CH * CH];
    __shared__ float sb[CH];
    __shared__ __align__(16) float2 ring[SLOTS * SLABS * TPB];  // 40KB

    {
        int t = threadIdx.x;
        if (t < CH * CH) sw[t] = w_proj[t];
        if (t < CH)      sb[t] = b_proj[t];
    }
    __syncthreads();

    const int tid = threadIdx.x;
    const int bid = blockIdx.x;
    const float2* q2 = reinterpret_cast<const float2*>(q);
    const float2* k2 = reinterpret_cast<const float2*>(k);
    const float2* v2 = reinterpret_cast<const float2*>(v);
    const uint32_t rb = (uint32_t)__cvta_generic_to_shared(ring);

    // Issue one group (5 slabs for A, 4 for B) and always commit.
    // Group id w: tile j = w>>5 (grid-stride), w&31: [0,16)=A(c), [16,32)=B(c).
    auto issue = [&](int w) {
        const int j = w >> 5;
        const int t = bid + j * GRID;
        if (t < NTILES) {
            const int w2 = w & 31;
            const int c  = w2 & (CH - 1);
            const int p  = t * TPB + tid;                     // float2 index
            const uint32_t dst = rb + (uint32_t)(((w & (SLOTS - 1)) * (SLABS * TPB) + tid) * sizeof(float2));
            if (w2 < CH) {
                cp8(dst + 0 * TPB * 8, q2 + c * V2 + p);
                cp8(dst + 1 * TPB * 8, k2 + (0 * CH + c) * V2 + p);
                cp8(dst + 2 * TPB * 8, k2 + (1 * CH + c) * V2 + p);
                cp8(dst + 3 * TPB * 8, k2 + (2 * CH + c) * V2 + p);
                cp8(dst + 4 * TPB * 8, k2 + (3 * CH + c) * V2 + p);
            } else {
                cp8(dst + 0 * TPB * 8, v2 + (0 * CH + c) * V2 + p);
                cp8(dst + 1 * TPB * 8, v2 + (1 * CH + c) * V2 + p);
                cp8(dst + 2 * TPB * 8, v2 + (2 * CH + c) * V2 + p);
                cp8(dst + 3 * TPB * 8, v2 + (3 * CH + c) * V2 + p);
            }
        }
        cp_commit();   // empty group past the end keeps wait_group counts aligned
    };

    // Prologue: 3 groups in flight
    issue(0); issue(1); issue(2);

    for (int j = 0; ; ++j) {
        const int t = bid + j * GRID;
        if (t >= NTILES) break;
        const int gbase = j * 32;                 // multiple of 32 -> slot = c&3
        const int p = t * TPB + tid;              // float2 index

        // ---- phase A: scores ----
        float2 sc[NCTX];
#pragma unroll
        for (int n = 0; n < NCTX; ++n) sc[n] = make_float2(0.f, 0.f);

#pragma unroll
        for (int c = 0; c < CH; ++c) {
            cp_wait2();
            __syncthreads();
            const int slotb = (c & (SLOTS - 1)) * (SLABS * TPB);
            const float2 qv = ring[slotb + tid];
#pragma unroll
            for (int n = 0; n < NCTX; ++n) {
                const float2 kv = ring[slotb + (1 + n) * TPB + tid];
                sc[n].x = fmaf(qv.x, kv.x, sc[n].x);
                sc[n].y = fmaf(qv.y, kv.y, sc[n].y);
            }
            issue(gbase + c + LOOKAHEAD);
        }

        // ---- softmax over n (scale 1/sqrt(16) = 0.25) ----
#pragma unroll
        for (int n = 0; n < NCTX; ++n) { sc[n].x *= 0.25f; sc[n].y *= 0.25f; }
        float2 mx = sc[0];
#pragma unroll
        for (int n = 1; n < NCTX; ++n) {
            mx.x = fmaxf(mx.x, sc[n].x);
            mx.y = fmaxf(mx.y, sc[n].y);
        }
        float2 ssum = make_float2(0.f, 0.f);
#pragma unroll
        for (int n = 0; n < NCTX; ++n) {
            sc[n].x = __expf(sc[n].x - mx.x);
            sc[n].y = __expf(sc[n].y - mx.y);
            ssum.x += sc[n].x;
            ssum.y += sc[n].y;
        }
        const float2 rs = make_float2(__frcp_rn(ssum.x), __frcp_rn(ssum.y));
#pragma unroll
        for (int n = 0; n < NCTX; ++n) { sc[n].x *= rs.x; sc[n].y *= rs.y; }

        // ---- phase B: x[c] = sum_n attn[n] * v[n][c] ----
        float2 x[CH];
#pragma unroll
        for (int c = 0; c < CH; ++c) {
            cp_wait2();
            __syncthreads();
            const int slotb = ((CH + c) & (SLOTS - 1)) * (SLABS * TPB);
            float2 a = make_float2(0.f, 0.f);
#pragma unroll
            for (int n = 0; n < NCTX; ++n) {
                const float2 vv = ring[slotb + n * TPB + tid];
                a.x = fmaf(sc[n].x, vv.x, a.x);
                a.y = fmaf(sc[n].y, vv.y, a.y);
            }
            x[c] = a;
            issue(gbase + CH + c + LOOKAHEAD);
        }

        // ---- phase C: out[o] = sum_c w[o][c] * x[c] + b[o] ----
        float* op = out + 2 * p;   // back to float index
#pragma unroll
        for (int o = 0; o < CH; ++o) {
            const float bo = sb[o];
            float2 acc = make_float2(bo, bo);
#pragma unroll
            for (int c = 0; c < CH; ++c) {
                const float wv = sw[o * CH + c];
                acc.x = fmaf(wv, x[c].x, acc.x);
                acc.y = fmaf(wv, x[c].y, acc.y);
            }
            __stcs(reinterpret_cast<float2*>(op + o * VOX), acc);
        }
    }
}

extern "C" void kernel_launch(void* const* d_in, const int* in_sizes, int n_in,
                              void* d_out, int out_size) {
    const float* q      = (const float*)d_in[0];
    const float* k      = (const float*)d_in[1];
    const float* v      = (const float*)d_in[2];
    const float* w_proj = (const float*)d_in[3];
    const float* b_proj = (const float*)d_in[4];
    float* out = (float*)d_out;

    volattn3d_kernel<<<GRID, TPB>>>(q, k, v, w_proj, b_proj, out);
}

// round 11
// speedup vs baseline: 1.0321x; 1.0321x over previous
#include <cuda_runtime.h>

// Problem constants (B=1, N=4, C=16, D=64, H=128, W=128)
#define NCTX 4
#define CH   16
#define VOX  (64 * 128 * 128)   // 1,048,576 voxels
#define VPT  2                  // voxels per thread (float2)
#define TPB  256
#define NSM  148
#define CTAS_PER_SM 4
#define GRID (NSM * CTAS_PER_SM)            // 592 persistent CTAs
#define NTILES (VOX / (TPB * VPT))          // 2048 tiles

__global__ __launch_bounds__(TPB, CTAS_PER_SM) void volattn3d_kernel(
    const float* __restrict__ q,      // [C][V]
    const float* __restrict__ k,      // [N][C][V]
    const float* __restrict__ v,      // [N][C][V]
    const float* __restrict__ w_proj, // [C][C]
    const float* __restrict__ b_proj, // [C]
    float* __restrict__ out)          // [C][V]
{
    __shared__ float sw[CH * CH];
    __shared__ float sb[CH];
    {
        int t = threadIdx.x;
        if (t < CH * CH) sw[t] = w_proj[t];
        if (t < CH)      sb[t] = b_proj[t];
    }
    __syncthreads();

    const int tid = threadIdx.x;

    int t = blockIdx.x;                       // current tile

    // ---------- prologue: phase A + softmax for the first tile ----------
    float2 sc[NCTX];
#pragma unroll
    for (int n = 0; n < NCTX; ++n) sc[n] = make_float2(0.f, 0.f);
    {
        const int p = (t * TPB + tid) * VPT;
        const float* qp = q + p;
        const float* kp = k + p;
#pragma unroll
        for (int c = 0; c < CH; ++c) {
            const float2 qv = __ldcs(reinterpret_cast<const float2*>(qp + c * VOX));
#pragma unroll
            for (int n = 0; n < NCTX; ++n) {
                const float2 kv = __ldcs(reinterpret_cast<const float2*>(kp + (n * CH + c) * VOX));
                sc[n].x = fmaf(qv.x, kv.x, sc[n].x);
                sc[n].y = fmaf(qv.y, kv.y, sc[n].y);
            }
        }
        // softmax (scale 1/sqrt(16) = 0.25)
#pragma unroll
        for (int n = 0; n < NCTX; ++n) { sc[n].x *= 0.25f; sc[n].y *= 0.25f; }
        float2 mx = sc[0];
#pragma unroll
        for (int n = 1; n < NCTX; ++n) {
            mx.x = fmaxf(mx.x, sc[n].x);
            mx.y = fmaxf(mx.y, sc[n].y);
        }
        float2 ssum = make_float2(0.f, 0.f);
#pragma unroll
        for (int n = 0; n < NCTX; ++n) {
            sc[n].x = __expf(sc[n].x - mx.x);
            sc[n].y = __expf(sc[n].y - mx.y);
            ssum.x += sc[n].x;
            ssum.y += sc[n].y;
        }
        const float2 rs = make_float2(__frcp_rn(ssum.x), __frcp_rn(ssum.y));
#pragma unroll
        for (int n = 0; n < NCTX; ++n) { sc[n].x *= rs.x; sc[n].y *= rs.y; }
    }

    // ---------- steady state: B(t) | A'(t+GRID) | C(t) | softmax ----------
#pragma unroll 1
    for (;;) {
        const int tn = t + GRID;                      // next tile
        const int p = (t * TPB + tid) * VPT;
        const float* vp = v + p;

        // ---- phase B: x[c] = sum_n attn[n] * v[n][c]  (64 loads) ----
        float2 x[CH];
#pragma unroll
        for (int c = 0; c < CH; ++c) x[c] = make_float2(0.f, 0.f);
#pragma unroll
        for (int n = 0; n < NCTX; ++n) {
#pragma unroll
            for (int c = 0; c < CH; ++c) {
                const float2 vv = __ldcs(reinterpret_cast<const float2*>(vp + (n * CH + c) * VOX));
                x[c].x = fmaf(sc[n].x, vv.x, x[c].x);
                x[c].y = fmaf(sc[n].y, vv.y, x[c].y);
            }
        }

        // ---- phase A' for next tile: issue 80 loads NOW so they are in
        //      flight during the load-free projection phase below ----
        float2 scn[NCTX];
#pragma unroll
        for (int n = 0; n < NCTX; ++n) scn[n] = make_float2(0.f, 0.f);
        if (tn < NTILES) {
            const int pn = (tn * TPB + tid) * VPT;
            const float* qp = q + pn;
            const float* kp = k + pn;
#pragma unroll
            for (int c = 0; c < CH; ++c) {
                const float2 qv = __ldcs(reinterpret_cast<const float2*>(qp + c * VOX));
#pragma unroll
                for (int n = 0; n < NCTX; ++n) {
                    const float2 kv = __ldcs(reinterpret_cast<const float2*>(kp + (n * CH + c) * VOX));
                    scn[n].x = fmaf(qv.x, kv.x, scn[n].x);
                    scn[n].y = fmaf(qv.y, kv.y, scn[n].y);
                }
            }
        }

        // ---- phase C: out[o] = sum_c w[o][c] * x[c] + b[o]  (no loads) ----
        float* op = out + p;
#pragma unroll
        for (int o = 0; o < CH; ++o) {
            const float bo = sb[o];
            float2 acc = make_float2(bo, bo);
#pragma unroll
            for (int c = 0; c < CH; ++c) {
                const float wv = sw[o * CH + c];
                acc.x = fmaf(wv, x[c].x, acc.x);
                acc.y = fmaf(wv, x[c].y, acc.y);
            }
            __stcs(reinterpret_cast<float2*>(op + o * VOX), acc);
        }

        if (tn >= NTILES) break;

        // ---- softmax for next tile ----
#pragma unroll
        for (int n = 0; n < NCTX; ++n) { scn[n].x *= 0.25f; scn[n].y *= 0.25f; }
        float2 mx = scn[0];
#pragma unroll
        for (int n = 1; n < NCTX; ++n) {
            mx.x = fmaxf(mx.x, scn[n].x);
            mx.y = fmaxf(mx.y, scn[n].y);
        }
        float2 ssum = make_float2(0.f, 0.f);
#pragma unroll
        for (int n = 0; n < NCTX; ++n) {
            scn[n].x = __expf(scn[n].x - mx.x);
            scn[n].y = __expf(scn[n].y - mx.y);
            ssum.x += scn[n].x;
            ssum.y += scn[n].y;
        }
        const float2 rs = make_float2(__frcp_rn(ssum.x), __frcp_rn(ssum.y));
#pragma unroll
        for (int n = 0; n < NCTX; ++n) {
            sc[n].x = scn[n].x * rs.x;
            sc[n].y = scn[n].y * rs.y;
        }

        t = tn;
    }
}

extern "C" void kernel_launch(void* const* d_in, const int* in_sizes, int n_in,
                              void* d_out, int out_size) {
    const float* q      = (const float*)d_in[0];
    const float* k      = (const float*)d_in[1];
    const float* v      = (const float*)d_in[2];
    const float* w_proj = (const float*)d_in[3];
    const float* b_proj = (const float*)d_in[4];
    float* out = (float*)d_out;

    volattn3d_kernel<<<GRID, TPB>>>(q, k, v, w_proj, b_proj, out);
}